// round 16
// baseline (speedup 1.0000x reference)
#include <cuda_runtime.h>
#include <cuda_bf16.h>

#define S_ 128
#define D_ 256
#define EPS_ (1e-6f)
#define HALF_WIN 4

// packed bf16x2 M^T (pairs along c): g_Mb[n*128 + c/2] = dot(Wq[c],Wk[n])/16
__device__ unsigned g_Mb[D_ * D_ / 2];
// packed bf16x2 Wv, d-major: g_Wvb[d*128 + kp] = (Wv[2kp][d], Wv[2kp+1][d])
__device__ unsigned g_Wvb[D_ * D_ / 2];
// u_g = Wv @ wg, u_l = Wv @ wl
__device__ float g_ug[D_];
__device__ float g_ul[D_];

// ---------------------------------------------------------------------------
__device__ __forceinline__ void mma_bf16(float* c, const unsigned* a, const unsigned* b) {
    asm volatile(
        "mma.sync.aligned.m16n8k16.row.col.f32.bf16.bf16.f32 "
        "{%0,%1,%2,%3}, {%4,%5,%6,%7}, {%8,%9}, {%0,%1,%2,%3};\n"
        : "+f"(c[0]), "+f"(c[1]), "+f"(c[2]), "+f"(c[3])
        : "r"(a[0]), "r"(a[1]), "r"(a[2]), "r"(a[3]), "r"(b[0]), "r"(b[1]));
}
__device__ __forceinline__ unsigned pack2(float lo, float hi) {
    __nv_bfloat162 t = __floats2bfloat162_rn(lo, hi);
    return *(unsigned*)&t;
}
__device__ __forceinline__ unsigned sptr(const void* p) {
    return (unsigned)__cvta_generic_to_shared(p);
}
__device__ __forceinline__ void ldm4(unsigned& r0, unsigned& r1, unsigned& r2,
                                     unsigned& r3, unsigned a) {
    asm volatile("ldmatrix.sync.aligned.m8n8.x4.shared.b16 {%0,%1,%2,%3}, [%4];"
                 : "=r"(r0), "=r"(r1), "=r"(r2), "=r"(r3) : "r"(a));
}
__device__ __forceinline__ void cpa16(void* dst, const void* src) {
    unsigned u = (unsigned)__cvta_generic_to_shared(dst);
    asm volatile("cp.async.cg.shared.global [%0], [%1], 16;\n" :: "r"(u), "l"(src));
}
__device__ __forceinline__ void cp_commit() { asm volatile("cp.async.commit_group;\n"); }
template <int N>
__device__ __forceinline__ void cp_wait() { asm volatile("cp.async.wait_group %0;\n" :: "n"(N)); }

// ---------------------------------------------------------------------------
// prep_all (parallel): blocks 0-31  -> M rows (8 rows per block, fp32 dots)
//                      blocks 32-159 -> Wv pack (d-major)
//                      blocks 160/161 -> u_g / u_l
// ---------------------------------------------------------------------------
__global__ __launch_bounds__(256) void prep_all(
    const float* __restrict__ Wq, const float* __restrict__ Wk,
    const float* __restrict__ Wv, const float* __restrict__ wg,
    const float* __restrict__ wl)
{
    const int bx = blockIdx.x;
    const int tid = threadIdx.x;
    if (bx >= 160) {
        const float* wv = (bx == 160) ? wg : wl;
        float* dst = (bx == 160) ? g_ug : g_ul;
        const float4* wv4 = (const float4*)(Wv + (size_t)tid * 256);
        float s = 0.0f;
        #pragma unroll 8
        for (int e = 0; e < 64; e++) {
            float4 w = wv4[e];
            s += w.x * wv[e*4] + w.y * wv[e*4+1] + w.z * wv[e*4+2] + w.w * wv[e*4+3];
        }
        dst[tid] = s;
        return;
    }
    if (bx >= 32) {
        int idx = (bx - 32) * 256 + tid;   // 0..32767
        int d = idx >> 7, kp = idx & 127;
        g_Wvb[idx] = pack2(Wv[(size_t)(2 * kp) * 256 + d],
                           Wv[(size_t)(2 * kp + 1) * 256 + d]);
        return;
    }
    // ---- M rows t0..t0+7 : M[t][c] = dot(Wk[t], Wq[c]) / 16 ----
    __shared__ float wk[8][260];
    const int t0 = bx * 8;
    #pragma unroll
    for (int i = 0; i < 8; i++) {
        int f = tid + i * 256;             // 0..2047
        int r = f >> 8, c = f & 255;
        wk[r][c] = Wk[(size_t)(t0 + r) * 256 + c];
    }
    __syncthreads();
    const int c = tid;                      // 0..255
    const float4* wq4 = (const float4*)(Wq + (size_t)c * 256);
    float acc[8];
    #pragma unroll
    for (int r = 0; r < 8; r++) acc[r] = 0.0f;
    #pragma unroll 4
    for (int e = 0; e < 64; e++) {
        float4 w = wq4[e];
        #pragma unroll
        for (int r = 0; r < 8; r++) {
            acc[r] += w.x * wk[r][e*4]   + w.y * wk[r][e*4+1]
                    + w.z * wk[r][e*4+2] + w.w * wk[r][e*4+3];
        }
    }
    #pragma unroll
    for (int r = 0; r < 8; r++) {
        float v = acc[r] * 0.0625f;
        float hi = __shfl_down_sync(0xffffffffu, v, 1);
        if (!(c & 1))
            g_Mb[(t0 + r) * 128 + (c >> 1)] = pack2(v, hi);
    }
}

// ---------------------------------------------------------------------------
// Fused kernel. smem (words):
//   U (Hs 128x132 / Vt 256x68)  17408
//   R0 8704 | STG 8704
//   WB 2 x 256 x 36             18432  (Wv chunks of 32 kp; later LN red)
//   vg,vl,hlog,af,bf 640 | sred 2048
// total 55936 words = 223744 B
// ---------------------------------------------------------------------------
#define HSTR 132
#define VTSTR 68
#define STGSTR 68
#define WVS 36
#define U_OFF 0
#define R0_OFF 17408
#define STG_OFF (R0_OFF + 128 * STGSTR)   // 26112
#define WB_OFF (STG_OFF + 128 * STGSTR)   // 34816
#define VG_OFF (WB_OFF + 2 * 256 * WVS)   // 53248
#define SRED_OFF (VG_OFF + 640)           // 53888
#define SM_FLOATS (SRED_OFF + 2048)       // 55936
#define SMEM_BYTES (SM_FLOATS * 4)

__device__ __forceinline__ void load_Mq(unsigned* dst, int h, int cq, int tid) {
    #pragma unroll
    for (int i = 0; i < 4; i++) {
        int f = tid + i * 512;
        int r = f >> 4;
        int c4 = (f & 15) << 2;
        cpa16(&dst[r * STGSTR + c4], &g_Mb[(h * 128 + r) * 128 + cq * 64 + c4]);
    }
    cp_commit();
}
// Wv chunk ck: 32 kp columns for all 256 d rows
__device__ __forceinline__ void load_WvC(unsigned* dst, int ck, int tid) {
    #pragma unroll
    for (int i = 0; i < 4; i++) {
        int f = tid + i * 512;       // 0..2047
        int d = f >> 3;              // 0..255
        int c4 = (f & 7) << 2;       // 0..28
        cpa16(&dst[d * WVS + c4], &g_Wvb[d * 128 + ck * 32 + c4]);
    }
    cp_commit();
}

// tacc0 += Hs[:, kp-half] @ M0 ; tacc1 += Hs[:, kp-half] @ M1
__device__ __forceinline__ void t_dual(
    float tacc0[2][4][4], float tacc1[2][4][4],
    unsigned aHs, unsigned bM0, unsigned bM1, int hs_kp)
{
    #pragma unroll
    for (int cc = 0; cc < 8; cc++) {
        const int kp = hs_kp + cc * 8;
        unsigned a[2][4], b0[4][2], b1[4][2], t0, t1, t2, t3;
        ldm4(a[0][0], a[0][1], a[0][2], a[0][3], aHs + kp * 4);
        ldm4(a[1][0], a[1][1], a[1][2], a[1][3], aHs + (16 * HSTR + kp) * 4);
        ldm4(t0, t1, t2, t3, bM0 + (cc * 8) * 4);
        b0[0][0] = t0; b0[0][1] = t1; b0[1][0] = t2; b0[1][1] = t3;
        ldm4(t0, t1, t2, t3, bM0 + (16 * STGSTR + cc * 8) * 4);
        b0[2][0] = t0; b0[2][1] = t1; b0[3][0] = t2; b0[3][1] = t3;
        ldm4(t0, t1, t2, t3, bM1 + (cc * 8) * 4);
        b1[0][0] = t0; b1[0][1] = t1; b1[1][0] = t2; b1[1][1] = t3;
        ldm4(t0, t1, t2, t3, bM1 + (16 * STGSTR + cc * 8) * 4);
        b1[2][0] = t0; b1[2][1] = t1; b1[3][0] = t2; b1[3][1] = t3;
        #pragma unroll
        for (int mt = 0; mt < 2; mt++)
            #pragma unroll
            for (int nt = 0; nt < 4; nt++) {
                mma_bf16(tacc0[mt][nt], a[mt], b0[nt]);
                mma_bf16(tacc1[mt][nt], a[mt], b1[nt]);
            }
    }
}

__device__ __forceinline__ void t_epi(
    const float tacc[2][4][4], unsigned* dst, int wm1, int wn1, int gi, int ti)
{
    #pragma unroll
    for (int mt = 0; mt < 2; mt++) {
        #pragma unroll
        for (int nt = 0; nt < 4; nt++) {
            int q = wm1 + mt * 16 + gi;
            int kp = (wn1 >> 1) + nt * 4 + ti;
            dst[q * STGSTR + kp]       = pack2(tacc[mt][nt][0], tacc[mt][nt][1]);
            dst[(q + 8) * STGSTR + kp] = pack2(tacc[mt][nt][2], tacc[mt][nt][3]);
        }
    }
}

__device__ __forceinline__ void gp_acc(
    float gacc[2][4][4], unsigned aTp, unsigned bHs, int h)
{
    #pragma unroll
    for (int ks = 0; ks < 8; ks++) {
        unsigned a[2][4], b[4][2], t0, t1, t2, t3;
        ldm4(a[0][0], a[0][1], a[0][2], a[0][3], aTp + (ks * 8) * 4);
        ldm4(a[1][0], a[1][1], a[1][2], a[1][3], aTp + (16 * STGSTR + ks * 8) * 4);
        ldm4(t0, t1, t2, t3, bHs + (h * 64 + ks * 8) * 4);
        b[0][0] = t0; b[0][1] = t1; b[1][0] = t2; b[1][1] = t3;
        ldm4(t0, t1, t2, t3, bHs + (16 * HSTR + h * 64 + ks * 8) * 4);
        b[2][0] = t0; b[2][1] = t1; b[3][0] = t2; b[3][1] = t3;
        #pragma unroll
        for (int mt = 0; mt < 2; mt++)
            #pragma unroll
            for (int nt = 0; nt < 4; nt++)
                mma_bf16(gacc[mt][nt], a[mt], b[nt]);
    }
}

__global__ __launch_bounds__(512) void fused_kernel(
    const float* __restrict__ H,
    const float* __restrict__ wh,
    const float* __restrict__ whb,
    const float* __restrict__ lng,
    const float* __restrict__ lnb,
    float* __restrict__ out)
{
    extern __shared__ float sm[];
    unsigned* Hs  = (unsigned*)(sm + U_OFF);
    unsigned* Vt  = (unsigned*)(sm + U_OFF);
    unsigned* R0  = (unsigned*)(sm + R0_OFF);
    unsigned* STG = (unsigned*)(sm + STG_OFF);
    float*    Wbf = sm + WB_OFF;
    unsigned* Wb  = (unsigned*)Wbf;
    float*    vg   = sm + VG_OFF;
    float*    vl   = vg + 128;
    float*    hlog = vl + 128;
    float*    af   = hlog + 128;
    float*    bf   = af + 128;
    float*    sred = sm + SRED_OFF;
    float*    red  = Wbf;

    const int bl = blockIdx.x;
    const float* Hb = H + (size_t)bl * S_ * D_;
    float* ob = out + (size_t)bl * S_ * D_;

    const int tid = threadIdx.x;
    const int lane = tid & 31;
    const int warp = tid >> 5;
    const int gi = lane >> 2, ti = lane & 3;
    const int lrA = lane & 15;
    const int lcA = (lane >> 4) << 2;
    const int lrB = (lane & 7) + ((lane >> 4) << 3);
    const int lcB = (lane & 8) ? 4 : 0;

    // ---------- phase 0: stage M(0,0)->R0, M(1,0)->STG; fused H pass --------
    load_Mq(R0, 0, 0, tid);
    load_Mq(STG, 1, 0, tid);
    {
        float whv[8], ugv[8], ulv[8];
        #pragma unroll
        for (int j = 0; j < 8; j++) {
            whv[j] = wh[lane * 8 + j];
            ugv[j] = g_ug[lane * 8 + j];
            ulv[j] = g_ul[lane * 8 + j];
        }
        const float whb0 = whb[0];
        #pragma unroll
        for (int rr = 0; rr < 8; rr++) {
            int q = warp * 8 + rr;
            float4 h0 = *(const float4*)&Hb[(size_t)q * 256 + lane * 8];
            float4 h1 = *(const float4*)&Hb[(size_t)q * 256 + lane * 8 + 4];
            uint4 w;
            w.x = pack2(h0.x, h0.y); w.y = pack2(h0.z, h0.w);
            w.z = pack2(h1.x, h1.y); w.w = pack2(h1.z, h1.w);
            *(uint4*)&Hs[q * HSTR + lane * 4] = w;
            float sh = h0.x*whv[0] + h0.y*whv[1] + h0.z*whv[2] + h0.w*whv[3]
                     + h1.x*whv[4] + h1.y*whv[5] + h1.z*whv[6] + h1.w*whv[7];
            float su = h0.x*ugv[0] + h0.y*ugv[1] + h0.z*ugv[2] + h0.w*ugv[3]
                     + h1.x*ugv[4] + h1.y*ugv[5] + h1.z*ugv[6] + h1.w*ugv[7];
            float sl = h0.x*ulv[0] + h0.y*ulv[1] + h0.z*ulv[2] + h0.w*ulv[3]
                     + h1.x*ulv[4] + h1.y*ulv[5] + h1.z*ulv[6] + h1.w*ulv[7];
            #pragma unroll
            for (int o = 16; o > 0; o >>= 1) {
                sh += __shfl_xor_sync(0xffffffffu, sh, o);
                su += __shfl_xor_sync(0xffffffffu, su, o);
                sl += __shfl_xor_sync(0xffffffffu, sl, o);
            }
            if (lane == 0) { hlog[q] = sh + whb0; vg[q] = su; vl[q] = sl; }
        }
    }
    cp_wait<0>(); __syncthreads();       // Hs + M(*,0) visible

    // ---------- phase 1: T (both n-halves, one A pass), then GP ----------
    const int wm1 = (warp >> 2) * 32;
    const int wn1 = (warp & 3) * 32;
    const unsigned aHsA = sptr(Hs) + (((wm1 + lrA) * HSTR + lcA) << 2);
    const unsigned bHsB = sptr(Hs) + (((wn1 + lrB) * HSTR + lcB) << 2);
    const unsigned aR0  = sptr(R0)  + (((wm1 + lrA) * STGSTR + lcA) << 2);
    const unsigned aSTG = sptr(STG) + (((wm1 + lrA) * STGSTR + lcA) << 2);
    const unsigned bR0  = sptr(R0)  + (((wn1 + lrB) * STGSTR + lcB) << 2);
    const unsigned bSTG = sptr(STG) + (((wn1 + lrB) * STGSTR + lcB) << 2);

    float gacc[2][4][4];
    {
        float tacc0[2][4][4], tacc1[2][4][4];
        #pragma unroll
        for (int mt = 0; mt < 2; mt++)
            #pragma unroll
            for (int nt = 0; nt < 4; nt++)
                #pragma unroll
                for (int r = 0; r < 4; r++) { tacc0[mt][nt][r] = 0.0f; tacc1[mt][nt][r] = 0.0f; }

        t_dual(tacc0, tacc1, aHsA, bR0, bSTG, 0);          // M(0,0), M(1,0)
        __syncthreads();
        load_Mq(R0, 0, 1, tid);
        load_Mq(STG, 1, 1, tid);
        cp_wait<0>(); __syncthreads();
        t_dual(tacc0, tacc1, aHsA, bR0, bSTG, 64);
        __syncthreads();
        t_epi(tacc0, R0, wm1, wn1, gi, ti);                // T0 -> R0
        t_epi(tacc1, STG, wm1, wn1, gi, ti);               // T1 -> STG
        __syncthreads();

        #pragma unroll
        for (int mt = 0; mt < 2; mt++)
            #pragma unroll
            for (int nt = 0; nt < 4; nt++)
                #pragma unroll
                for (int r = 0; r < 4; r++) gacc[mt][nt][r] = 0.0f;
        gp_acc(gacc, aR0, bHsB, 0);
        gp_acc(gacc, aSTG, bHsB, 1);
        __syncthreads();
    }

    // issue Wv chunk 0 (overlaps softmax)
    load_WvC(Wb, 0, tid);

    // ---------- softmax + gate on gacc registers ----------
    {
        float st[4][4];
        #pragma unroll
        for (int i = 0; i < 4; i++)
            #pragma unroll
            for (int k = 0; k < 4; k++) st[i][k] = 0.0f;

        #pragma unroll
        for (int mt = 0; mt < 2; mt++) {
            #pragma unroll
            for (int nt = 0; nt < 4; nt++) {
                int col = wn1 + nt * 8 + 2 * ti;
                float vg0 = vg[col], vg1 = vg[col + 1];
                float vl0 = vl[col], vl1 = vl[col + 1];
                #pragma unroll
                for (int rbit = 0; rbit < 2; rbit++) {
                    int row = wm1 + mt * 16 + gi + rbit * 8;
                    float e0 = __expf(gacc[mt][nt][rbit * 2]);
                    float e1 = __expf(gacc[mt][nt][rbit * 2 + 1]);
                    gacc[mt][nt][rbit * 2]     = e0;
                    gacc[mt][nt][rbit * 2 + 1] = e1;
                    int idx = mt * 2 + rbit;
                    st[idx][0] += e0 + e1;
                    st[idx][1] += e0 * vg0 + e1 * vg1;
                    int d0 = col - row;
                    bool b0 = (d0 >= -HALF_WIN) && (d0 <= HALF_WIN);
                    bool b1 = (d0 + 1 >= -HALF_WIN) && (d0 + 1 <= HALF_WIN);
                    if (b0) { st[idx][2] += e0; st[idx][3] += e0 * vl0; }
                    if (b1) { st[idx][2] += e1; st[idx][3] += e1 * vl1; }
                }
            }
        }
        #pragma unroll
        for (int i = 0; i < 4; i++)
            #pragma unroll
            for (int k = 0; k < 4; k++) {
                st[i][k] += __shfl_xor_sync(0xffffffffu, st[i][k], 1);
                st[i][k] += __shfl_xor_sync(0xffffffffu, st[i][k], 2);
            }
        if (ti == 0) {
            const int wslot = warp & 3;
            #pragma unroll
            for (int mt = 0; mt < 2; mt++)
                #pragma unroll
                for (int rbit = 0; rbit < 2; rbit++) {
                    int row = wm1 + mt * 16 + gi + rbit * 8;
                    int idx = mt * 2 + rbit;
                    *(float4*)&sred[(wslot * 128 + row) * 4] =
                        make_float4(st[idx][0], st[idx][1], st[idx][2], st[idx][3]);
                }
        }
        __syncthreads();
        if (tid < 128) {
            int row = tid;
            float4 p0 = *(float4*)&sred[(0 * 128 + row) * 4];
            float4 p1 = *(float4*)&sred[(1 * 128 + row) * 4];
            float4 p2 = *(float4*)&sred[(2 * 128 + row) * 4];
            float4 p3 = *(float4*)&sred[(3 * 128 + row) * 4];
            float s  = p0.x + p1.x + p2.x + p3.x;
            float sg = p0.y + p1.y + p2.y + p3.y;
            float ls = p0.z + p1.z + p2.z + p3.z;
            float ll = p0.w + p1.w + p2.w + p3.w;
            float inv = 1.0f / s, linv = 1.0f / ls;
            float zz = hlog[row] + sg * inv + ll * linv;
            float gt = 1.0f / (1.0f + __expf(-zz));
            af[row] = (1.0f - gt) * inv;
            bf[row] = gt * linv;
        }
        __syncthreads();
        // PC pack -> STG
        #pragma unroll
        for (int mt = 0; mt < 2; mt++) {
            #pragma unroll
            for (int nt = 0; nt < 4; nt++) {
                int col = wn1 + nt * 8 + 2 * ti;
                int kp = (wn1 >> 1) + nt * 4 + ti;
                #pragma unroll
                for (int rbit = 0; rbit < 2; rbit++) {
                    int row = wm1 + mt * 16 + gi + rbit * 8;
                    float a = af[row], b = bf[row];
                    int d0 = col - row;
                    bool b0 = (d0 >= -HALF_WIN) && (d0 <= HALF_WIN);
                    bool b1 = (d0 + 1 >= -HALF_WIN) && (d0 + 1 <= HALF_WIN);
                    float pc0 = gacc[mt][nt][rbit * 2]     * (a + (b0 ? b : 0.0f));
                    float pc1 = gacc[mt][nt][rbit * 2 + 1] * (a + (b1 ? b : 0.0f));
                    STG[row * STGSTR + kp] = pack2(pc0, pc1);
                }
            }
        }
    }
    __syncthreads();

    // ---------- phase 2: V = Hs @ Wv (4 chunks of 32 kp, double-buffered) ---
    {
        const int wd = (warp & 3) * 64;
        const unsigned bWv0 = sptr(Wb) + ((lrB * WVS + lcB) << 2);
        float vacc[2][8][4];
        #pragma unroll
        for (int mt = 0; mt < 2; mt++)
            #pragma unroll
            for (int nt = 0; nt < 8; nt++)
                #pragma unroll
                for (int r = 0; r < 4; r++) vacc[mt][nt][r] = 0.0f;

        #pragma unroll 1
        for (int ck = 0; ck < 4; ck++) {
            cp_wait<0>();
            __syncthreads();
            if (ck < 3)
                load_WvC(Wb + ((ck + 1) & 1) * 256 * WVS, ck + 1, tid);
            const unsigned bWv = bWv0 + (ck & 1) * 256 * WVS * 4;
            #pragma unroll
            for (int s = 0; s < 4; s++) {
                const int kp0 = ck * 32 + s * 8;
                unsigned a[2][4], b[8][2], t0, t1, t2, t3;
                ldm4(a[0][0], a[0][1], a[0][2], a[0][3], aHsA + kp0 * 4);
                ldm4(a[1][0], a[1][1], a[1][2], a[1][3], aHsA + (16 * HSTR + kp0) * 4);
                #pragma unroll
                for (int pr = 0; pr < 4; pr++) {
                    ldm4(t0, t1, t2, t3, bWv + (((wd + pr * 16) * WVS) + s * 8) * 4);
                    b[2 * pr][0] = t0; b[2 * pr][1] = t1;
                    b[2 * pr + 1][0] = t2; b[2 * pr + 1][1] = t3;
                }
                #pragma unroll
                for (int mt = 0; mt < 2; mt++)
                    #pragma unroll
                    for (int nt = 0; nt < 8; nt++)
                        mma_bf16(vacc[mt][nt], a[mt], b[nt]);
            }
        }
        __syncthreads();   // all Hs reads done

        // V -> Vt (overwrite Hs)
        #pragma unroll
        for (int mt = 0; mt < 2; mt++) {
            #pragma unroll
            for (int nt = 0; nt < 8; nt++) {
                int q = wm1 + mt * 16 + gi;
                int d = wd + nt * 8 + 2 * ti;
                float p0 = __shfl_down_sync(0xffffffffu, vacc[mt][nt][0], 4);
                float p1 = __shfl_down_sync(0xffffffffu, vacc[mt][nt][1], 4);
                float p2 = __shfl_down_sync(0xffffffffu, vacc[mt][nt][2], 4);
                float p3 = __shfl_down_sync(0xffffffffu, vacc[mt][nt][3], 4);
                if (!(gi & 1)) {
                    int qp = q >> 1, qp8 = (q + 8) >> 1;
                    Vt[d * VTSTR + qp]        = pack2(vacc[mt][nt][0], p0);
                    Vt[(d + 1) * VTSTR + qp]  = pack2(vacc[mt][nt][1], p1);
                    Vt[d * VTSTR + qp8]       = pack2(vacc[mt][nt][2], p2);
                    Vt[(d + 1) * VTSTR + qp8] = pack2(vacc[mt][nt][3], p3);
                }
            }
        }
    }
    __syncthreads();

    // ---------- PV + residual + LN ----------
    {
        const int wd3 = (warp >> 2) * 64;
        const int wq3 = (warp & 3) * 32;
        const unsigned aVt = sptr(Vt) + (((wd3 + lrA) * VTSTR + lcA) << 2);
        const unsigned bPC = sptr(STG) + (((wq3 + lrB) * STGSTR + lcB) << 2);
        float acc[4][4][4];
        #pragma unroll
        for (int mt = 0; mt < 4; mt++)
            #pragma unroll
            for (int nt = 0; nt < 4; nt++)
                #pragma unroll
                for (int r = 0; r < 4; r++) acc[mt][nt][r] = 0.0f;

        #pragma unroll
        for (int ks = 0; ks < 8; ks++) {
            unsigned a[4][4], b[4][2], t0, t1, t2, t3;
            #pragma unroll
            for (int mt = 0; mt < 4; mt++)
                ldm4(a[mt][0], a[mt][1], a[mt][2], a[mt][3],
                     aVt + (mt * 16 * VTSTR + ks * 8) * 4);
            ldm4(t0, t1, t2, t3, bPC + (ks * 8) * 4);
            b[0][0] = t0; b[0][1] = t1; b[1][0] = t2; b[1][1] = t3;
            ldm4(t0, t1, t2, t3, bPC + (16 * STGSTR + ks * 8) * 4);
            b[2][0] = t0; b[2][1] = t1; b[3][0] = t2; b[3][1] = t3;
            #pragma unroll
            for (int mt = 0; mt < 4; mt++)
                #pragma unroll
                for (int nt = 0; nt < 4; nt++)
                    mma_bf16(acc[mt][nt], a[mt], b[nt]);
        }

        float s1[4][2], s2[4][2];
        #pragma unroll
        for (int nt = 0; nt < 4; nt++)
            #pragma unroll
            for (int j = 0; j < 2; j++) { s1[nt][j] = 0.0f; s2[nt][j] = 0.0f; }

        #pragma unroll
        for (int mt = 0; mt < 4; mt++) {
            int d0 = wd3 + mt * 16 + gi, d1 = d0 + 8;
            #pragma unroll
            for (int nt = 0; nt < 4; nt++) {
                int q0 = wq3 + nt * 8 + 2 * ti, q1 = q0 + 1;
                acc[mt][nt][0] += Hb[(size_t)q0 * 256 + d0];
                acc[mt][nt][1] += Hb[(size_t)q1 * 256 + d0];
                acc[mt][nt][2] += Hb[(size_t)q0 * 256 + d1];
                acc[mt][nt][3] += Hb[(size_t)q1 * 256 + d1];
                s1[nt][0] += acc[mt][nt][0] + acc[mt][nt][2];
                s1[nt][1] += acc[mt][nt][1] + acc[mt][nt][3];
                s2[nt][0] += acc[mt][nt][0]*acc[mt][nt][0] + acc[mt][nt][2]*acc[mt][nt][2];
                s2[nt][1] += acc[mt][nt][1]*acc[mt][nt][1] + acc[mt][nt][3]*acc[mt][nt][3];
            }
        }
        #pragma unroll
        for (int nt = 0; nt < 4; nt++)
            #pragma unroll
            for (int j = 0; j < 2; j++)
                #pragma unroll
                for (int o = 4; o <= 16; o <<= 1) {
                    s1[nt][j] += __shfl_xor_sync(0xffffffffu, s1[nt][j], o);
                    s2[nt][j] += __shfl_xor_sync(0xffffffffu, s2[nt][j], o);
                }
        const int wslot = warp >> 2;
        if (gi == 0) {
            #pragma unroll
            for (int nt = 0; nt < 4; nt++)
                #pragma unroll
                for (int j = 0; j < 2; j++) {
                    int q = wq3 + nt * 8 + 2 * ti + j;
                    red[(wslot * 128 + q) * 2]     = s1[nt][j];
                    red[(wslot * 128 + q) * 2 + 1] = s2[nt][j];
                }
        }
        __syncthreads();

        float lg0[4], lg1[4], lb0[4], lb1[4];
        #pragma unroll
        for (int mt = 0; mt < 4; mt++) {
            int d0 = wd3 + mt * 16 + gi;
            lg0[mt] = lng[d0]; lg1[mt] = lng[d0 + 8];
            lb0[mt] = lnb[d0]; lb1[mt] = lnb[d0 + 8];
        }
        #pragma unroll
        for (int nt = 0; nt < 4; nt++) {
            #pragma unroll
            for (int j = 0; j < 2; j++) {
                int q = wq3 + nt * 8 + 2 * ti + j;
                float t1 = red[q*2] + red[(128+q)*2] + red[(256+q)*2] + red[(384+q)*2];
                float t2 = red[q*2+1] + red[(128+q)*2+1] + red[(256+q)*2+1] + red[(384+q)*2+1];
                float mu = t1 * (1.0f / 256.0f);
                float var = t2 * (1.0f / 256.0f) - mu * mu;
                float rstd = rsqrtf(var + EPS_);
                #pragma unroll
                for (int mt = 0; mt < 4; mt++) {
                    int d0 = wd3 + mt * 16 + gi;
                    ob[(size_t)q * 256 + d0]     = lg0[mt] * (acc[mt][nt][j]   - mu) * rstd + lb0[mt];
                    ob[(size_t)q * 256 + d0 + 8] = lg1[mt] * (acc[mt][nt][2+j] - mu) * rstd + lb1[mt];
                }
            }
        }
    }
}

// ---------------------------------------------------------------------------
extern "C" void kernel_launch(void* const* d_in, const int* in_sizes, int n_in,
                              void* d_out, int out_size)
{
    const float* H   = (const float*)d_in[0];
    const float* Wq  = (const float*)d_in[2];
    const float* Wk  = (const float*)d_in[3];
    const float* Wv  = (const float*)d_in[4];
    const float* wh  = (const float*)d_in[5];
    const float* whb = (const float*)d_in[6];
    const float* wg  = (const float*)d_in[7];
    const float* wl  = (const float*)d_in[8];
    const float* lng = (const float*)d_in[9];
    const float* lnb = (const float*)d_in[10];
    float* out = (float*)d_out;

    cudaFuncSetAttribute(fused_kernel,
                         cudaFuncAttributeMaxDynamicSharedMemorySize, SMEM_BYTES);

    prep_all<<<162, 256>>>(Wq, Wk, Wv, wg, wl);
    fused_kernel<<<512, 512, SMEM_BYTES>>>(H, wh, whb, lng, lnb, out);
}

// round 17
// speedup vs baseline: 1.0552x; 1.0552x over previous
#include <cuda_runtime.h>
#include <cuda_bf16.h>

#define S_ 128
#define D_ 256
#define EPS_ (1e-6f)
#define HALF_WIN 4

// packed bf16x2 M^T (pairs along c): g_Mb[n*128 + c/2] = dot(Wq[c],Wk[n])/16
__device__ unsigned g_Mb[D_ * D_ / 2];
// packed bf16x2 Wv, d-major: g_Wvb[d*128 + kp] = (Wv[2kp][d], Wv[2kp+1][d])
__device__ unsigned g_Wvb[D_ * D_ / 2];
// u_g = Wv @ wg, u_l = Wv @ wl
__device__ float g_ug[D_];
__device__ float g_ul[D_];

// ---------------------------------------------------------------------------
__device__ __forceinline__ void mma_bf16(float* c, const unsigned* a, const unsigned* b) {
    asm volatile(
        "mma.sync.aligned.m16n8k16.row.col.f32.bf16.bf16.f32 "
        "{%0,%1,%2,%3}, {%4,%5,%6,%7}, {%8,%9}, {%0,%1,%2,%3};\n"
        : "+f"(c[0]), "+f"(c[1]), "+f"(c[2]), "+f"(c[3])
        : "r"(a[0]), "r"(a[1]), "r"(a[2]), "r"(a[3]), "r"(b[0]), "r"(b[1]));
}
__device__ __forceinline__ void mma_tf32(float* c, const unsigned* a, const unsigned* b) {
    asm volatile(
        "mma.sync.aligned.m16n8k8.row.col.f32.tf32.tf32.f32 "
        "{%0,%1,%2,%3}, {%4,%5,%6,%7}, {%8,%9}, {%0,%1,%2,%3};\n"
        : "+f"(c[0]), "+f"(c[1]), "+f"(c[2]), "+f"(c[3])
        : "r"(a[0]), "r"(a[1]), "r"(a[2]), "r"(a[3]), "r"(b[0]), "r"(b[1]));
}
__device__ __forceinline__ unsigned pack2(float lo, float hi) {
    __nv_bfloat162 t = __floats2bfloat162_rn(lo, hi);
    return *(unsigned*)&t;
}
__device__ __forceinline__ unsigned sptr(const void* p) {
    return (unsigned)__cvta_generic_to_shared(p);
}
__device__ __forceinline__ void ldm4(unsigned& r0, unsigned& r1, unsigned& r2,
                                     unsigned& r3, unsigned a) {
    asm volatile("ldmatrix.sync.aligned.m8n8.x4.shared.b16 {%0,%1,%2,%3}, [%4];"
                 : "=r"(r0), "=r"(r1), "=r"(r2), "=r"(r3) : "r"(a));
}
__device__ __forceinline__ void cpa16(void* dst, const void* src) {
    unsigned u = (unsigned)__cvta_generic_to_shared(dst);
    asm volatile("cp.async.cg.shared.global [%0], [%1], 16;\n" :: "r"(u), "l"(src));
}
__device__ __forceinline__ void cp_commit() { asm volatile("cp.async.commit_group;\n"); }
template <int N>
__device__ __forceinline__ void cp_wait() { asm volatile("cp.async.wait_group %0;\n" :: "n"(N)); }

// ---------------------------------------------------------------------------
// prep_all: blocks 0-7   -> M tiles (128m x 64n, tf32, double-buffered)
//           blocks 8-135 -> Wv pack (d-major)
//           blocks 136/137 -> u_g / u_l
// ---------------------------------------------------------------------------
#define PM_STR 36
#define PREP_SMEM ((2 * 128 * PM_STR + 2 * 64 * PM_STR) * 4)   // 55296 B

__global__ __launch_bounds__(256) void prep_all(
    const float* __restrict__ Wq, const float* __restrict__ Wk,
    const float* __restrict__ Wv, const float* __restrict__ wg,
    const float* __restrict__ wl)
{
    const int bx = blockIdx.x;
    const int tid = threadIdx.x;
    if (bx >= 136) {
        const float* wv = (bx == 136) ? wg : wl;
        float* dst = (bx == 136) ? g_ug : g_ul;
        const float4* wv4 = (const float4*)(Wv + (size_t)tid * 256);
        float s = 0.0f;
        #pragma unroll 8
        for (int e = 0; e < 64; e++) {
            float4 w = wv4[e];
            s += w.x * wv[e*4] + w.y * wv[e*4+1] + w.z * wv[e*4+2] + w.w * wv[e*4+3];
        }
        dst[tid] = s;
        return;
    }
    if (bx >= 8) {
        int idx = (bx - 8) * 256 + tid;   // 0..32767
        int d = idx >> 7, kp = idx & 127;
        g_Wvb[idx] = pack2(Wv[(size_t)(2 * kp) * 256 + d],
                           Wv[(size_t)(2 * kp + 1) * 256 + d]);
        return;
    }
    // ---- M tile (128m x 64n), K=256, BK=32, double-buffered ----
    extern __shared__ float ps[];
    float* As = ps;                            // [2][128][36]  Wk rows (m)
    float* Bs = ps + 2 * 128 * PM_STR;         // [2][64][36]   Wq rows (n)
    const int m0 = (bx >> 2) * 128;            // t
    const int n0 = (bx & 3) * 64;              // c
    const int lane = tid & 31, warp = tid >> 5;
    const int gi = lane >> 2, ti = lane & 3;
    const int wm = (warp >> 1) * 32;           // 4 m-groups
    const int wn = (warp & 1) * 32;            // 2 n-groups

    float acc[2][4][4];
    #pragma unroll
    for (int mt = 0; mt < 2; mt++)
        #pragma unroll
        for (int nt = 0; nt < 4; nt++)
            #pragma unroll
            for (int r = 0; r < 4; r++) acc[mt][nt][r] = 0.0f;

    // prefetch stage 0
    #pragma unroll
    for (int i = 0; i < 4; i++) {
        int f = tid + i * 256;
        int row = f >> 3, kc = (f & 7) << 2;
        cpa16(&As[row * PM_STR + kc], &Wk[(size_t)(m0 + row) * 256 + kc]);
    }
    #pragma unroll
    for (int i = 0; i < 2; i++) {
        int f = tid + i * 256;
        int row = f >> 3, kc = (f & 7) << 2;
        cpa16(&Bs[row * PM_STR + kc], &Wq[(size_t)(n0 + row) * 256 + kc]);
    }
    cp_commit();

    for (int kt = 0; kt < 8; kt++) {
        if (kt < 7) {
            const int k0 = (kt + 1) * 32;
            float* Ad = As + ((kt + 1) & 1) * 128 * PM_STR;
            float* Bd = Bs + ((kt + 1) & 1) * 64 * PM_STR;
            #pragma unroll
            for (int i = 0; i < 4; i++) {
                int f = tid + i * 256;
                int row = f >> 3, kc = (f & 7) << 2;
                cpa16(&Ad[row * PM_STR + kc], &Wk[(size_t)(m0 + row) * 256 + k0 + kc]);
            }
            #pragma unroll
            for (int i = 0; i < 2; i++) {
                int f = tid + i * 256;
                int row = f >> 3, kc = (f & 7) << 2;
                cpa16(&Bd[row * PM_STR + kc], &Wq[(size_t)(n0 + row) * 256 + k0 + kc]);
            }
            cp_commit();
            cp_wait<1>();
        } else {
            cp_wait<0>();
        }
        __syncthreads();

        const float* Ab = As + (kt & 1) * 128 * PM_STR;
        const float* Bb = Bs + (kt & 1) * 64 * PM_STR;
        #pragma unroll
        for (int kk = 0; kk < 4; kk++) {
            const int kb = kk * 8 + ti;
            unsigned a[2][4], b[4][2];
            #pragma unroll
            for (int mt = 0; mt < 2; mt++) {
                int r = wm + mt * 16 + gi;
                a[mt][0] = __float_as_uint(Ab[r * PM_STR + kb]);
                a[mt][1] = __float_as_uint(Ab[(r + 8) * PM_STR + kb]);
                a[mt][2] = __float_as_uint(Ab[r * PM_STR + kb + 4]);
                a[mt][3] = __float_as_uint(Ab[(r + 8) * PM_STR + kb + 4]);
            }
            #pragma unroll
            for (int nt = 0; nt < 4; nt++) {
                int n = wn + nt * 8 + gi;
                b[nt][0] = __float_as_uint(Bb[n * PM_STR + kb]);
                b[nt][1] = __float_as_uint(Bb[n * PM_STR + kb + 4]);
            }
            #pragma unroll
            for (int mt = 0; mt < 2; mt++)
                #pragma unroll
                for (int nt = 0; nt < 4; nt++)
                    mma_tf32(acc[mt][nt], a[mt], b[nt]);
        }
        __syncthreads();
    }

    #pragma unroll
    for (int mt = 0; mt < 2; mt++) {
        #pragma unroll
        for (int nt = 0; nt < 4; nt++) {
            int q = m0 + wm + mt * 16 + gi;
            int n = n0 + wn + nt * 8 + 2 * ti;
            g_Mb[q * 128 + (n >> 1)] =
                pack2(acc[mt][nt][0] * 0.0625f, acc[mt][nt][1] * 0.0625f);
            g_Mb[(q + 8) * 128 + (n >> 1)] =
                pack2(acc[mt][nt][2] * 0.0625f, acc[mt][nt][3] * 0.0625f);
        }
    }
}

// ---------------------------------------------------------------------------
// Fused kernel — identical to R16 (measured 129.2 us).
// ---------------------------------------------------------------------------
#define HSTR 132
#define VTSTR 68
#define STGSTR 68
#define WVS 36
#define U_OFF 0
#define R0_OFF 17408
#define STG_OFF (R0_OFF + 128 * STGSTR)   // 26112
#define WB_OFF (STG_OFF + 128 * STGSTR)   // 34816
#define VG_OFF (WB_OFF + 2 * 256 * WVS)   // 53248
#define SRED_OFF (VG_OFF + 640)           // 53888
#define SM_FLOATS (SRED_OFF + 2048)       // 55936
#define SMEM_BYTES (SM_FLOATS * 4)

__device__ __forceinline__ void load_Mq(unsigned* dst, int h, int cq, int tid) {
    #pragma unroll
    for (int i = 0; i < 4; i++) {
        int f = tid + i * 512;
        int r = f >> 4;
        int c4 = (f & 15) << 2;
        cpa16(&dst[r * STGSTR + c4], &g_Mb[(h * 128 + r) * 128 + cq * 64 + c4]);
    }
    cp_commit();
}
__device__ __forceinline__ void load_WvC(unsigned* dst, int ck, int tid) {
    #pragma unroll
    for (int i = 0; i < 4; i++) {
        int f = tid + i * 512;
        int d = f >> 3;
        int c4 = (f & 7) << 2;
        cpa16(&dst[d * WVS + c4], &g_Wvb[d * 128 + ck * 32 + c4]);
    }
    cp_commit();
}

__device__ __forceinline__ void t_dual(
    float tacc0[2][4][4], float tacc1[2][4][4],
    unsigned aHs, unsigned bM0, unsigned bM1, int hs_kp)
{
    #pragma unroll
    for (int cc = 0; cc < 8; cc++) {
        const int kp = hs_kp + cc * 8;
        unsigned a[2][4], b0[4][2], b1[4][2], t0, t1, t2, t3;
        ldm4(a[0][0], a[0][1], a[0][2], a[0][3], aHs + kp * 4);
        ldm4(a[1][0], a[1][1], a[1][2], a[1][3], aHs + (16 * HSTR + kp) * 4);
        ldm4(t0, t1, t2, t3, bM0 + (cc * 8) * 4);
        b0[0][0] = t0; b0[0][1] = t1; b0[1][0] = t2; b0[1][1] = t3;
        ldm4(t0, t1, t2, t3, bM0 + (16 * STGSTR + cc * 8) * 4);
        b0[2][0] = t0; b0[2][1] = t1; b0[3][0] = t2; b0[3][1] = t3;
        ldm4(t0, t1, t2, t3, bM1 + (cc * 8) * 4);
        b1[0][0] = t0; b1[0][1] = t1; b1[1][0] = t2; b1[1][1] = t3;
        ldm4(t0, t1, t2, t3, bM1 + (16 * STGSTR + cc * 8) * 4);
        b1[2][0] = t0; b1[2][1] = t1; b1[3][0] = t2; b1[3][1] = t3;
        #pragma unroll
        for (int mt = 0; mt < 2; mt++)
            #pragma unroll
            for (int nt = 0; nt < 4; nt++) {
                mma_bf16(tacc0[mt][nt], a[mt], b0[nt]);
                mma_bf16(tacc1[mt][nt], a[mt], b1[nt]);
            }
    }
}

__device__ __forceinline__ void t_epi(
    const float tacc[2][4][4], unsigned* dst, int wm1, int wn1, int gi, int ti)
{
    #pragma unroll
    for (int mt = 0; mt < 2; mt++) {
        #pragma unroll
        for (int nt = 0; nt < 4; nt++) {
            int q = wm1 + mt * 16 + gi;
            int kp = (wn1 >> 1) + nt * 4 + ti;
            dst[q * STGSTR + kp]       = pack2(tacc[mt][nt][0], tacc[mt][nt][1]);
            dst[(q + 8) * STGSTR + kp] = pack2(tacc[mt][nt][2], tacc[mt][nt][3]);
        }
    }
}

__device__ __forceinline__ void gp_acc(
    float gacc[2][4][4], unsigned aTp, unsigned bHs, int h)
{
    #pragma unroll
    for (int ks = 0; ks < 8; ks++) {
        unsigned a[2][4], b[4][2], t0, t1, t2, t3;
        ldm4(a[0][0], a[0][1], a[0][2], a[0][3], aTp + (ks * 8) * 4);
        ldm4(a[1][0], a[1][1], a[1][2], a[1][3], aTp + (16 * STGSTR + ks * 8) * 4);
        ldm4(t0, t1, t2, t3, bHs + (h * 64 + ks * 8) * 4);
        b[0][0] = t0; b[0][1] = t1; b[1][0] = t2; b[1][1] = t3;
        ldm4(t0, t1, t2, t3, bHs + (16 * HSTR + h * 64 + ks * 8) * 4);
        b[2][0] = t0; b[2][1] = t1; b[3][0] = t2; b[3][1] = t3;
        #pragma unroll
        for (int mt = 0; mt < 2; mt++)
            #pragma unroll
            for (int nt = 0; nt < 4; nt++)
                mma_bf16(gacc[mt][nt], a[mt], b[nt]);
    }
}

__global__ __launch_bounds__(512) void fused_kernel(
    const float* __restrict__ H,
    const float* __restrict__ wh,
    const float* __restrict__ whb,
    const float* __restrict__ lng,
    const float* __restrict__ lnb,
    float* __restrict__ out)
{
    extern __shared__ float sm[];
    unsigned* Hs  = (unsigned*)(sm + U_OFF);
    unsigned* Vt  = (unsigned*)(sm + U_OFF);
    unsigned* R0  = (unsigned*)(sm + R0_OFF);
    unsigned* STG = (unsigned*)(sm + STG_OFF);
    float*    Wbf = sm + WB_OFF;
    unsigned* Wb  = (unsigned*)Wbf;
    float*    vg   = sm + VG_OFF;
    float*    vl   = vg + 128;
    float*    hlog = vl + 128;
    float*    af   = hlog + 128;
    float*    bf   = af + 128;
    float*    sred = sm + SRED_OFF;
    float*    red  = Wbf;

    const int bl = blockIdx.x;
    const float* Hb = H + (size_t)bl * S_ * D_;
    float* ob = out + (size_t)bl * S_ * D_;

    const int tid = threadIdx.x;
    const int lane = tid & 31;
    const int warp = tid >> 5;
    const int gi = lane >> 2, ti = lane & 3;
    const int lrA = lane & 15;
    const int lcA = (lane >> 4) << 2;
    const int lrB = (lane & 7) + ((lane >> 4) << 3);
    const int lcB = (lane & 8) ? 4 : 0;

    // ---------- phase 0 ----------
    load_Mq(R0, 0, 0, tid);
    load_Mq(STG, 1, 0, tid);
    {
        float whv[8], ugv[8], ulv[8];
        #pragma unroll
        for (int j = 0; j < 8; j++) {
            whv[j] = wh[lane * 8 + j];
            ugv[j] = g_ug[lane * 8 + j];
            ulv[j] = g_ul[lane * 8 + j];
        }
        const float whb0 = whb[0];
        #pragma unroll
        for (int rr = 0; rr < 8; rr++) {
            int q = warp * 8 + rr;
            float4 h0 = *(const float4*)&Hb[(size_t)q * 256 + lane * 8];
            float4 h1 = *(const float4*)&Hb[(size_t)q * 256 + lane * 8 + 4];
            uint4 w;
            w.x = pack2(h0.x, h0.y); w.y = pack2(h0.z, h0.w);
            w.z = pack2(h1.x, h1.y); w.w = pack2(h1.z, h1.w);
            *(uint4*)&Hs[q * HSTR + lane * 4] = w;
            float sh = h0.x*whv[0] + h0.y*whv[1] + h0.z*whv[2] + h0.w*whv[3]
                     + h1.x*whv[4] + h1.y*whv[5] + h1.z*whv[6] + h1.w*whv[7];
            float su = h0.x*ugv[0] + h0.y*ugv[1] + h0.z*ugv[2] + h0.w*ugv[3]
                     + h1.x*ugv[4] + h1.y*ugv[5] + h1.z*ugv[6] + h1.w*ugv[7];
            float sl = h0.x*ulv[0] + h0.y*ulv[1] + h0.z*ulv[2] + h0.w*ulv[3]
                     + h1.x*ulv[4] + h1.y*ulv[5] + h1.z*ulv[6] + h1.w*ulv[7];
            #pragma unroll
            for (int o = 16; o > 0; o >>= 1) {
                sh += __shfl_xor_sync(0xffffffffu, sh, o);
                su += __shfl_xor_sync(0xffffffffu, su, o);
                sl += __shfl_xor_sync(0xffffffffu, sl, o);
            }
            if (lane == 0) { hlog[q] = sh + whb0; vg[q] = su; vl[q] = sl; }
        }
    }
    cp_wait<0>(); __syncthreads();

    // ---------- phase 1 ----------
    const int wm1 = (warp >> 2) * 32;
    const int wn1 = (warp & 3) * 32;
    const unsigned aHsA = sptr(Hs) + (((wm1 + lrA) * HSTR + lcA) << 2);
    const unsigned bHsB = sptr(Hs) + (((wn1 + lrB) * HSTR + lcB) << 2);
    const unsigned aR0  = sptr(R0)  + (((wm1 + lrA) * STGSTR + lcA) << 2);
    const unsigned aSTG = sptr(STG) + (((wm1 + lrA) * STGSTR + lcA) << 2);
    const unsigned bR0  = sptr(R0)  + (((wn1 + lrB) * STGSTR + lcB) << 2);
    const unsigned bSTG = sptr(STG) + (((wn1 + lrB) * STGSTR + lcB) << 2);

    float gacc[2][4][4];
    {
        float tacc0[2][4][4], tacc1[2][4][4];
        #pragma unroll
        for (int mt = 0; mt < 2; mt++)
            #pragma unroll
            for (int nt = 0; nt < 4; nt++)
                #pragma unroll
                for (int r = 0; r < 4; r++) { tacc0[mt][nt][r] = 0.0f; tacc1[mt][nt][r] = 0.0f; }

        t_dual(tacc0, tacc1, aHsA, bR0, bSTG, 0);
        __syncthreads();
        load_Mq(R0, 0, 1, tid);
        load_Mq(STG, 1, 1, tid);
        cp_wait<0>(); __syncthreads();
        t_dual(tacc0, tacc1, aHsA, bR0, bSTG, 64);
        __syncthreads();
        t_epi(tacc0, R0, wm1, wn1, gi, ti);
        t_epi(tacc1, STG, wm1, wn1, gi, ti);
        __syncthreads();

        #pragma unroll
        for (int mt = 0; mt < 2; mt++)
            #pragma unroll
            for (int nt = 0; nt < 4; nt++)
                #pragma unroll
                for (int r = 0; r < 4; r++) gacc[mt][nt][r] = 0.0f;
        gp_acc(gacc, aR0, bHsB, 0);
        gp_acc(gacc, aSTG, bHsB, 1);
        __syncthreads();
    }

    load_WvC(Wb, 0, tid);

    // ---------- softmax + gate ----------
    {
        float st[4][4];
        #pragma unroll
        for (int i = 0; i < 4; i++)
            #pragma unroll
            for (int k = 0; k < 4; k++) st[i][k] = 0.0f;

        #pragma unroll
        for (int mt = 0; mt < 2; mt++) {
            #pragma unroll
            for (int nt = 0; nt < 4; nt++) {
                int col = wn1 + nt * 8 + 2 * ti;
                float vg0 = vg[col], vg1 = vg[col + 1];
                float vl0 = vl[col], vl1 = vl[col + 1];
                #pragma unroll
                for (int rbit = 0; rbit < 2; rbit++) {
                    int row = wm1 + mt * 16 + gi + rbit * 8;
                    float e0 = __expf(gacc[mt][nt][rbit * 2]);
                    float e1 = __expf(gacc[mt][nt][rbit * 2 + 1]);
                    gacc[mt][nt][rbit * 2]     = e0;
                    gacc[mt][nt][rbit * 2 + 1] = e1;
                    int idx = mt * 2 + rbit;
                    st[idx][0] += e0 + e1;
                    st[idx][1] += e0 * vg0 + e1 * vg1;
                    int d0 = col - row;
                    bool b0 = (d0 >= -HALF_WIN) && (d0 <= HALF_WIN);
                    bool b1 = (d0 + 1 >= -HALF_WIN) && (d0 + 1 <= HALF_WIN);
                    if (b0) { st[idx][2] += e0; st[idx][3] += e0 * vl0; }
                    if (b1) { st[idx][2] += e1; st[idx][3] += e1 * vl1; }
                }
            }
        }
        #pragma unroll
        for (int i = 0; i < 4; i++)
            #pragma unroll
            for (int k = 0; k < 4; k++) {
                st[i][k] += __shfl_xor_sync(0xffffffffu, st[i][k], 1);
                st[i][k] += __shfl_xor_sync(0xffffffffu, st[i][k], 2);
            }
        if (ti == 0) {
            const int wslot = warp & 3;
            #pragma unroll
            for (int mt = 0; mt < 2; mt++)
                #pragma unroll
                for (int rbit = 0; rbit < 2; rbit++) {
                    int row = wm1 + mt * 16 + gi + rbit * 8;
                    int idx = mt * 2 + rbit;
                    *(float4*)&sred[(wslot * 128 + row) * 4] =
                        make_float4(st[idx][0], st[idx][1], st[idx][2], st[idx][3]);
                }
        }
        __syncthreads();
        if (tid < 128) {
            int row = tid;
            float4 p0 = *(float4*)&sred[(0 * 128 + row) * 4];
            float4 p1 = *(float4*)&sred[(1 * 128 + row) * 4];
            float4 p2 = *(float4*)&sred[(2 * 128 + row) * 4];
            float4 p3 = *(float4*)&sred[(3 * 128 + row) * 4];
            float s  = p0.x + p1.x + p2.x + p3.x;
            float sg = p0.y + p1.y + p2.y + p3.y;
            float ls = p0.z + p1.z + p2.z + p3.z;
            float ll = p0.w + p1.w + p2.w + p3.w;
            float inv = 1.0f / s, linv = 1.0f / ls;
            float zz = hlog[row] + sg * inv + ll * linv;
            float gt = 1.0f / (1.0f + __expf(-zz));
            af[row] = (1.0f - gt) * inv;
            bf[row] = gt * linv;
        }
        __syncthreads();
        #pragma unroll
        for (int mt = 0; mt < 2; mt++) {
            #pragma unroll
            for (int nt = 0; nt < 4; nt++) {
                int col = wn1 + nt * 8 + 2 * ti;
                int kp = (wn1 >> 1) + nt * 4 + ti;
                #pragma unroll
                for (int rbit = 0; rbit < 2; rbit++) {
                    int row = wm1 + mt * 16 + gi + rbit * 8;
                    float a = af[row], b = bf[row];
                    int d0 = col - row;
                    bool b0 = (d0 >= -HALF_WIN) && (d0 <= HALF_WIN);
                    bool b1 = (d0 + 1 >= -HALF_WIN) && (d0 + 1 <= HALF_WIN);
                    float pc0 = gacc[mt][nt][rbit * 2]     * (a + (b0 ? b : 0.0f));
                    float pc1 = gacc[mt][nt][rbit * 2 + 1] * (a + (b1 ? b : 0.0f));
                    STG[row * STGSTR + kp] = pack2(pc0, pc1);
                }
            }
        }
    }
    __syncthreads();

    // ---------- phase 2: V = Hs @ Wv ----------
    {
        const int wd = (warp & 3) * 64;
        const unsigned bWv0 = sptr(Wb) + ((lrB * WVS + lcB) << 2);
        float vacc[2][8][4];
        #pragma unroll
        for (int mt = 0; mt < 2; mt++)
            #pragma unroll
            for (int nt = 0; nt < 8; nt++)
                #pragma unroll
                for (int r = 0; r < 4; r++) vacc[mt][nt][r] = 0.0f;

        #pragma unroll 1
        for (int ck = 0; ck < 4; ck++) {
            cp_wait<0>();
            __syncthreads();
            if (ck < 3)
                load_WvC(Wb + ((ck + 1) & 1) * 256 * WVS, ck + 1, tid);
            const unsigned bWv = bWv0 + (ck & 1) * 256 * WVS * 4;
            #pragma unroll
            for (int s = 0; s < 4; s++) {
                const int kp0 = ck * 32 + s * 8;
                unsigned a[2][4], b[8][2], t0, t1, t2, t3;
                ldm4(a[0][0], a[0][1], a[0][2], a[0][3], aHsA + kp0 * 4);
                ldm4(a[1][0], a[1][1], a[1][2], a[1][3], aHsA + (16 * HSTR + kp0) * 4);
                #pragma unroll
                for (int pr = 0; pr < 4; pr++) {
                    ldm4(t0, t1, t2, t3, bWv + (((wd + pr * 16) * WVS) + s * 8) * 4);
                    b[2 * pr][0] = t0; b[2 * pr][1] = t1;
                    b[2 * pr + 1][0] = t2; b[2 * pr + 1][1] = t3;
                }
                #pragma unroll
                for (int mt = 0; mt < 2; mt++)
                    #pragma unroll
                    for (int nt = 0; nt < 8; nt++)
                        mma_bf16(vacc[mt][nt], a[mt], b[nt]);
            }
        }
        __syncthreads();

        #pragma unroll
        for (int mt = 0; mt < 2; mt++) {
            #pragma unroll
            for (int nt = 0; nt < 8; nt++) {
                int q = wm1 + mt * 16 + gi;
                int d = wd + nt * 8 + 2 * ti;
                float p0 = __shfl_down_sync(0xffffffffu, vacc[mt][nt][0], 4);
                float p1 = __shfl_down_sync(0xffffffffu, vacc[mt][nt][1], 4);
                float p2 = __shfl_down_sync(0xffffffffu, vacc[mt][nt][2], 4);
                float p3 = __shfl_down_sync(0xffffffffu, vacc[mt][nt][3], 4);
                if (!(gi & 1)) {
                    int qp = q >> 1, qp8 = (q + 8) >> 1;
                    Vt[d * VTSTR + qp]        = pack2(vacc[mt][nt][0], p0);
                    Vt[(d + 1) * VTSTR + qp]  = pack2(vacc[mt][nt][1], p1);
                    Vt[d * VTSTR + qp8]       = pack2(vacc[mt][nt][2], p2);
                    Vt[(d + 1) * VTSTR + qp8] = pack2(vacc[mt][nt][3], p3);
                }
            }
        }
    }
    __syncthreads();

    // ---------- PV + residual + LN ----------
    {
        const int wd3 = (warp >> 2) * 64;
        const int wq3 = (warp & 3) * 32;
        const unsigned aVt = sptr(Vt) + (((wd3 + lrA) * VTSTR + lcA) << 2);
        const unsigned bPC = sptr(STG) + (((wq3 + lrB) * STGSTR + lcB) << 2);
        float acc[4][4][4];
        #pragma unroll
        for (int mt = 0; mt < 4; mt++)
            #pragma unroll
            for (int nt = 0; nt < 4; nt++)
                #pragma unroll
                for (int r = 0; r < 4; r++) acc[mt][nt][r] = 0.0f;

        #pragma unroll
        for (int ks = 0; ks < 8; ks++) {
            unsigned a[4][4], b[4][2], t0, t1, t2, t3;
            #pragma unroll
            for (int mt = 0; mt < 4; mt++)
                ldm4(a[mt][0], a[mt][1], a[mt][2], a[mt][3],
                     aVt + (mt * 16 * VTSTR + ks * 8) * 4);
            ldm4(t0, t1, t2, t3, bPC + (ks * 8) * 4);
            b[0][0] = t0; b[0][1] = t1; b[1][0] = t2; b[1][1] = t3;
            ldm4(t0, t1, t2, t3, bPC + (16 * STGSTR + ks * 8) * 4);
            b[2][0] = t0; b[2][1] = t1; b[3][0] = t2; b[3][1] = t3;
            #pragma unroll
            for (int mt = 0; mt < 4; mt++)
                #pragma unroll
                for (int nt = 0; nt < 4; nt++)
                    mma_bf16(acc[mt][nt], a[mt], b[nt]);
        }

        float s1[4][2], s2[4][2];
        #pragma unroll
        for (int nt = 0; nt < 4; nt++)
            #pragma unroll
            for (int j = 0; j < 2; j++) { s1[nt][j] = 0.0f; s2[nt][j] = 0.0f; }

        #pragma unroll
        for (int mt = 0; mt < 4; mt++) {
            int d0 = wd3 + mt * 16 + gi, d1 = d0 + 8;
            #pragma unroll
            for (int nt = 0; nt < 4; nt++) {
                int q0 = wq3 + nt * 8 + 2 * ti, q1 = q0 + 1;
                acc[mt][nt][0] += Hb[(size_t)q0 * 256 + d0];
                acc[mt][nt][1] += Hb[(size_t)q1 * 256 + d0];
                acc[mt][nt][2] += Hb[(size_t)q0 * 256 + d1];
                acc[mt][nt][3] += Hb[(size_t)q1 * 256 + d1];
                s1[nt][0] += acc[mt][nt][0] + acc[mt][nt][2];
                s1[nt][1] += acc[mt][nt][1] + acc[mt][nt][3];
                s2[nt][0] += acc[mt][nt][0]*acc[mt][nt][0] + acc[mt][nt][2]*acc[mt][nt][2];
                s2[nt][1] += acc[mt][nt][1]*acc[mt][nt][1] + acc[mt][nt][3]*acc[mt][nt][3];
            }
        }
        #pragma unroll
        for (int nt = 0; nt < 4; nt++)
            #pragma unroll
            for (int j = 0; j < 2; j++)
                #pragma unroll
                for (int o = 4; o <= 16; o <<= 1) {
                    s1[nt][j] += __shfl_xor_sync(0xffffffffu, s1[nt][j], o);
                    s2[nt][j] += __shfl_xor_sync(0xffffffffu, s2[nt][j], o);
                }
        const int wslot = warp >> 2;
        if (gi == 0) {
            #pragma unroll
            for (int nt = 0; nt < 4; nt++)
                #pragma unroll
                for (int j = 0; j < 2; j++) {
                    int q = wq3 + nt * 8 + 2 * ti + j;
                    red[(wslot * 128 + q) * 2]     = s1[nt][j];
                    red[(wslot * 128 + q) * 2 + 1] = s2[nt][j];
                }
        }
        __syncthreads();

        float lg0[4], lg1[4], lb0[4], lb1[4];
        #pragma unroll
        for (int mt = 0; mt < 4; mt++) {
            int d0 = wd3 + mt * 16 + gi;
            lg0[mt] = lng[d0]; lg1[mt] = lng[d0 + 8];
            lb0[mt] = lnb[d0]; lb1[mt] = lnb[d0 + 8];
        }
        #pragma unroll
        for (int nt = 0; nt < 4; nt++) {
            #pragma unroll
            for (int j = 0; j < 2; j++) {
                int q = wq3 + nt * 8 + 2 * ti + j;
                float t1 = red[q*2] + red[(128+q)*2] + red[(256+q)*2] + red[(384+q)*2];
                float t2 = red[q*2+1] + red[(128+q)*2+1] + red[(256+q)*2+1] + red[(384+q)*2+1];
                float mu = t1 * (1.0f / 256.0f);
                float var = t2 * (1.0f / 256.0f) - mu * mu;
                float rstd = rsqrtf(var + EPS_);
                #pragma unroll
                for (int mt = 0; mt < 4; mt++) {
                    int d0 = wd3 + mt * 16 + gi;
                    ob[(size_t)q * 256 + d0]     = lg0[mt] * (acc[mt][nt][j]   - mu) * rstd + lb0[mt];
                    ob[(size_t)q * 256 + d0 + 8] = lg1[mt] * (acc[mt][nt][2+j] - mu) * rstd + lb1[mt];
                }
            }
        }
    }
}

// ---------------------------------------------------------------------------
extern "C" void kernel_launch(void* const* d_in, const int* in_sizes, int n_in,
                              void* d_out, int out_size)
{
    const float* H   = (const float*)d_in[0];
    const float* Wq  = (const float*)d_in[2];
    const float* Wk  = (const float*)d_in[3];
    const float* Wv  = (const float*)d_in[4];
    const float* wh  = (const float*)d_in[5];
    const float* whb = (const float*)d_in[6];
    const float* wg  = (const float*)d_in[7];
    const float* wl  = (const float*)d_in[8];
    const float* lng = (const float*)d_in[9];
    const float* lnb = (const float*)d_in[10];
    float* out = (float*)d_out;

    cudaFuncSetAttribute(prep_all,
                         cudaFuncAttributeMaxDynamicSharedMemorySize, PREP_SMEM);
    cudaFuncSetAttribute(fused_kernel,
                         cudaFuncAttributeMaxDynamicSharedMemorySize, SMEM_BYTES);

    prep_all<<<138, 256, PREP_SMEM>>>(Wq, Wk, Wv, wg, wl);
    fused_kernel<<<512, 512, SMEM_BYTES>>>(H, wh, whb, lng, lnb, out);
}